// round 2
// baseline (speedup 1.0000x reference)
#include <cuda_runtime.h>
#include <math.h>
#include <stdint.h>

#define BB 4096
#define DD 256
#define CC 5994
#define SCALE 30.0f
#define COSM 0.9800665778412416f   // cos(0.2)
#define SINM 0.19866933079506122f  // sin(0.2)
#define EPSC 1e-7f

#define ROWS 16
#define THREADS 256
#define CPT 2
#define CSTRIDE (THREADS * CPT)                 // 512
#define NCH ((CC + CSTRIDE - 1) / CSTRIDE)      // 12

typedef unsigned long long u64;

__device__ int   g_is64;
__device__ int   g_lab[BB];
__device__ float g_invnx[BB];
__device__ float g_invnw[CC];
__device__ float g_rowloss[BB];
__device__ float g_rowhit[BB];

// ---------------------------------------------------------------------------
// Label dtype detection: if the label tensor is int64, all odd 32-bit words
// (high halves of nonneg values < 5994) are zero. If int32, odd words are
// actual labels (all-zero has probability ~0). Reads only the first 16 KB,
// which is in-bounds for either layout.
__global__ void detect_kernel(const unsigned int* __restrict__ p) {
    int any = 0;
    for (int i = 1 + 2 * (int)threadIdx.x; i < BB; i += 2 * (int)blockDim.x)
        any |= (p[i] != 0u);
    int r = __syncthreads_or(any);
    if (threadIdx.x == 0) g_is64 = (r == 0) ? 1 : 0;
}

__global__ void conv_labels(const int* __restrict__ p) {
    int i = blockIdx.x * blockDim.x + threadIdx.x;
    if (i < BB) g_lab[i] = g_is64 ? p[2 * i] : p[i];
}

// ---------------------------------------------------------------------------
// Row inverse norms of x: one warp per row.
__global__ void xnorm_kernel(const float* __restrict__ x) {
    int warp = (blockIdx.x * blockDim.x + threadIdx.x) >> 5;
    int lane = threadIdx.x & 31;
    if (warp >= BB) return;
    const float* xr = x + (size_t)warp * DD;
    float s = 0.f;
    #pragma unroll
    for (int k = lane; k < DD; k += 32) { float v = xr[k]; s += v * v; }
    #pragma unroll
    for (int o = 16; o; o >>= 1) s += __shfl_xor_sync(~0u, s, o);
    if (lane == 0) g_invnx[warp] = 1.0f / fmaxf(sqrtf(s), 1e-12f);
}

// Column inverse norms of W: one thread per column (coalesced across k).
__global__ void wnorm_kernel(const float* __restrict__ W) {
    int c = blockIdx.x * blockDim.x + threadIdx.x;
    if (c >= CC) return;
    float s = 0.f;
    const float* wp = W + c;
    #pragma unroll 4
    for (int k = 0; k < DD; k++) { float v = wp[(size_t)k * CC]; s += v * v; }
    g_invnw[c] = 1.0f / fmaxf(sqrtf(s), 1e-12f);
}

// ---------------------------------------------------------------------------
// f32x2 packed helpers
__device__ __forceinline__ u64 pack2(float a, float b) {
    u64 r; asm("mov.b64 %0, {%1, %2};" : "=l"(r) : "f"(a), "f"(b)); return r;
}
__device__ __forceinline__ void unpack2(u64 v, float& a, float& b) {
    asm("mov.b64 {%0, %1}, %2;" : "=f"(a), "=f"(b) : "l"(v));
}
__device__ __forceinline__ u64 fma2(u64 a, u64 b, u64 c) {
    u64 d; asm("fma.rn.f32x2 %0, %1, %2, %3;" : "=l"(d) : "l"(a), "l"(b), "l"(c));
    return d;
}

// ---------------------------------------------------------------------------
// Fused normalized-GEMM + margin + online softmax + argmax.
// Block = 16 rows; each thread owns 2 consecutive classes per chunk iteration.
// Accumulators pack 2 adjacent rows into one f32x2 (FFMA2 doubles fp32 rate).
__global__ __launch_bounds__(THREADS, 1)
void main_kernel(const float* __restrict__ x, const float* __restrict__ Wm) {
    __shared__ float xsT[DD][ROWS];     // transposed, row-pairs adjacent (16 KB)
    __shared__ float tgt_s[ROWS];
    __shared__ int   labs_s[ROWS];
    __shared__ float red_m[ROWS][8];
    __shared__ float red_s[ROWS][8];
    __shared__ int   red_c[ROWS][8];

    const int tid = threadIdx.x;
    const int r0  = blockIdx.x * ROWS;

    // Load x tile (coalesced), normalize, store transposed.
    for (int idx = tid; idx < ROWS * DD; idx += THREADS) {
        int r = idx >> 8;
        int k = idx & (DD - 1);
        xsT[k][r] = x[(size_t)r0 * DD + idx] * g_invnx[r0 + r];
    }
    if (tid < ROWS) { labs_s[tid] = g_lab[r0 + tid]; tgt_s[tid] = 0.f; }
    __syncthreads();

    int lab[ROWS];
    #pragma unroll
    for (int r = 0; r < ROWS; r++) lab[r] = labs_s[r];

    float m[ROWS], s[ROWS]; int bc[ROWS];
    #pragma unroll
    for (int r = 0; r < ROWS; r++) { m[r] = -INFINITY; s[r] = 0.f; bc[r] = 0x7fffffff; }

#define UPDATE(r, ctexpr, cidx)                                           \
    {                                                                     \
        float ctv = fminf(fmaxf((ctexpr), -1.0f + EPSC), 1.0f + EPSC);    \
        float lg;                                                         \
        if ((cidx) == lab[r]) {                                           \
            float s2 = 1.0f - ctv * ctv;                                  \
            float sn = (s2 > 0.f) ? sqrtf(s2) : 0.f;                      \
            lg = (ctv * COSM - sn * SINM) * SCALE;                        \
            tgt_s[r] = lg;                                                \
        } else {                                                          \
            lg = ctv * SCALE;                                             \
        }                                                                 \
        if (lg > m[r]) {                                                  \
            s[r] = s[r] * __expf(m[r] - lg) + 1.0f;                       \
            m[r] = lg; bc[r] = (cidx);                                    \
        } else {                                                          \
            s[r] += __expf(lg - m[r]);                                    \
        }                                                                 \
    }

    for (int ch = 0; ch < NCH; ch++) {
        const int c0 = ch * CSTRIDE + 2 * tid;     // even; c0+1 valid iff c0 < CC
        const int cl = (c0 < CC) ? c0 : 0;         // safe load column
        const float* wp = Wm + cl;

        u64 accA[ROWS / 2], accB[ROWS / 2];
        #pragma unroll
        for (int j = 0; j < ROWS / 2; j++) { accA[j] = 0ull; accB[j] = 0ull; }

        #pragma unroll 4
        for (int k = 0; k < DD; k++) {
            float2 wv = *reinterpret_cast<const float2*>(wp + (size_t)k * CC);
            u64 w0 = pack2(wv.x, wv.x);
            u64 w1 = pack2(wv.y, wv.y);
            const u64* xk = reinterpret_cast<const u64*>(&xsT[k][0]);
            #pragma unroll
            for (int j = 0; j < ROWS / 2; j++) {
                u64 xp = xk[j];                 // broadcast LDS.64: rows 2j,2j+1
                accA[j] = fma2(xp, w0, accA[j]);
                accB[j] = fma2(xp, w1, accB[j]);
            }
        }

        if (c0 < CC) {
            float iw0 = g_invnw[c0];
            float iw1 = g_invnw[c0 + 1];
            #pragma unroll
            for (int j = 0; j < ROWS / 2; j++) {
                float a0, a1, b0, b1;
                unpack2(accA[j], a0, a1);
                unpack2(accB[j], b0, b1);
                UPDATE(2 * j,     a0 * iw0, c0);
                UPDATE(2 * j + 1, a1 * iw0, c0);
                UPDATE(2 * j,     b0 * iw1, c0 + 1);
                UPDATE(2 * j + 1, b1 * iw1, c0 + 1);
            }
        }
    }
#undef UPDATE

    __syncthreads();   // tgt_s visible to the finishing threads

    const int lane = tid & 31, wid = tid >> 5;
    #pragma unroll
    for (int r = 0; r < ROWS; r++) {
        float mm = m[r], ss = s[r]; int cc = bc[r];
        #pragma unroll
        for (int o = 16; o; o >>= 1) {
            float om = __shfl_xor_sync(~0u, mm, o);
            float os = __shfl_xor_sync(~0u, ss, o);
            int   oc = __shfl_xor_sync(~0u, cc, o);
            float M = fmaxf(mm, om);
            float ns = ss * __expf(mm - M) + os * __expf(om - M);
            if (om > mm || (om == mm && oc < cc)) cc = oc;
            mm = M; ss = ns;
        }
        if (lane == 0) { red_m[r][wid] = mm; red_s[r][wid] = ss; red_c[r][wid] = cc; }
    }
    __syncthreads();

    if (tid < ROWS) {
        const int r = tid;
        float mm = red_m[r][0], ss = red_s[r][0]; int cc = red_c[r][0];
        #pragma unroll
        for (int w = 1; w < 8; w++) {
            float om = red_m[r][w], os = red_s[r][w]; int oc = red_c[r][w];
            float M = fmaxf(mm, om);
            ss = ss * __expf(mm - M) + os * __expf(om - M);
            if (om > mm || (om == mm && oc < cc)) cc = oc;
            mm = M;
        }
        float lse = mm + logf(ss);
        g_rowloss[r0 + r] = lse - tgt_s[r];
        g_rowhit[r0 + r]  = (cc == labs_s[r]) ? 1.0f : 0.0f;
    }
}

// ---------------------------------------------------------------------------
__global__ void finalize_kernel(float* __restrict__ out) {
    __shared__ float sl[1024];
    __shared__ float sh[1024];
    int tid = threadIdx.x;
    float l = 0.f, h = 0.f;
    for (int i = tid; i < BB; i += 1024) { l += g_rowloss[i]; h += g_rowhit[i]; }
    sl[tid] = l; sh[tid] = h;
    __syncthreads();
    for (int o = 512; o; o >>= 1) {
        if (tid < o) { sl[tid] += sl[tid + o]; sh[tid] += sh[tid + o]; }
        __syncthreads();
    }
    if (tid == 0) {
        out[0] = sl[0] / (float)BB;
        out[1] = sh[0] * (100.0f / (float)BB);
    }
}

// ---------------------------------------------------------------------------
extern "C" void kernel_launch(void* const* d_in, const int* in_sizes, int n_in,
                              void* d_out, int out_size) {
    const float* x   = (const float*)d_in[0];   // [4096, 256]
    const float* W   = (const float*)d_in[1];   // [256, 5994]
    const int*   lab = (const int*)d_in[2];     // [4096] (int32 or int64 — detected)

    detect_kernel<<<1, 256>>>((const unsigned int*)lab);
    conv_labels<<<(BB + 255) / 256, 256>>>(lab);
    xnorm_kernel<<<(BB * 32) / 256, 256>>>(x);
    wnorm_kernel<<<(CC + 255) / 256, 256>>>(W);
    main_kernel<<<BB / ROWS, THREADS>>>(x, W);
    finalize_kernel<<<1, 1024>>>((float*)d_out);
}

// round 8
// speedup vs baseline: 5.4596x; 5.4596x over previous
#include <cuda_runtime.h>
#include <math.h>
#include <stdint.h>

#define BB 4096
#define DD 256
#define CC 5994
#define CPAD 6016
#define NTILES 47
#define MTILES 32
#define SCL 30.0f
#define COSM 0.9800665778412416f
#define SINM 0.19866933079506122f
#define EPSC 1e-7f

#define KC 64          // k-chunk per smem stage
#define AST 68         // smem row stride (floats): bank=(4*row+k)%32, conflict-free
#define SMEM_DYN (2 * 128 * AST * 4)

typedef unsigned int u32;

__device__ int   g_is64;
__device__ int   g_lab[BB];
__device__ float g_xn[BB * DD];          // normalized x, tf32-rounded
__device__ float g_wt[CPAD * DD];        // W^T, normalized cols, tf32-rounded, zero-padded
__device__ float g_tgt[BB];              // margin logit of the label class per row
__device__ float g_pm[BB * NTILES];      // partial max
__device__ float g_ps[BB * NTILES];      // partial sum
__device__ int   g_pc[BB * NTILES];      // partial argmax (global class)
__device__ float g_rowloss[BB];
__device__ float g_rowhit[BB];

__device__ __forceinline__ float to_tf32(float v) {
    u32 u; asm("cvt.rna.tf32.f32 %0, %1;" : "=r"(u) : "f"(v));
    return __uint_as_float(u);
}

// m16n8k8 tf32 HMMA (baseline sm_80+ PTX; compiles for plain sm_103)
__device__ __forceinline__ void mma8(float* d, const u32* a, u32 b0, u32 b1) {
    asm volatile(
        "mma.sync.aligned.m16n8k8.row.col.f32.tf32.tf32.f32 "
        "{%0,%1,%2,%3}, {%4,%5,%6,%7}, {%8,%9}, {%0,%1,%2,%3};"
        : "+f"(d[0]), "+f"(d[1]), "+f"(d[2]), "+f"(d[3])
        : "r"(a[0]), "r"(a[1]), "r"(a[2]), "r"(a[3]), "r"(b0), "r"(b1));
}

// ---------------------------------------------------------------------------
// Label dtype detection (int64 vs int32) + gather
__global__ void detect_kernel(const u32* __restrict__ p) {
    int any = 0;
    for (int i = 1 + 2 * (int)threadIdx.x; i < BB; i += 2 * (int)blockDim.x)
        any |= (p[i] != 0u);
    int r = __syncthreads_or(any);
    if (threadIdx.x == 0) g_is64 = (r == 0) ? 1 : 0;
}
__global__ void conv_labels(const int* __restrict__ p) {
    int i = blockIdx.x * blockDim.x + threadIdx.x;
    if (i < BB) g_lab[i] = g_is64 ? p[2 * i] : p[i];
}

// Normalize rows of x, round to tf32. One warp per row.
__global__ void prep_x(const float* __restrict__ x) {
    int warp = (blockIdx.x * blockDim.x + threadIdx.x) >> 5;
    int lane = threadIdx.x & 31;
    if (warp >= BB) return;
    const float* xr = x + (size_t)warp * DD;
    float v[8]; float s = 0.f;
    #pragma unroll
    for (int j = 0; j < 8; j++) { v[j] = xr[lane + 32 * j]; s += v[j] * v[j]; }
    #pragma unroll
    for (int o = 16; o; o >>= 1) s += __shfl_xor_sync(~0u, s, o);
    float inv = 1.0f / fmaxf(sqrtf(s), 1e-12f);
    #pragma unroll
    for (int j = 0; j < 8; j++) g_xn[warp * DD + lane + 32 * j] = to_tf32(v[j] * inv);
}

// Transpose W [256, 5994] -> g_wt [6016, 256] (raw fp32, zero padded).
__global__ void wt_transpose(const float* __restrict__ W) {
    __shared__ float t[32][33];
    int bx = blockIdx.x, by = blockIdx.y;
    int tx = threadIdx.x, ty = threadIdx.y;
    #pragma unroll
    for (int i = ty; i < 32; i += 8) {
        int k = by * 32 + i, c = bx * 32 + tx;
        t[i][tx] = (c < CC) ? W[(size_t)k * CC + c] : 0.f;
    }
    __syncthreads();
    #pragma unroll
    for (int i = ty; i < 32; i += 8)
        g_wt[(size_t)(bx * 32 + i) * DD + by * 32 + tx] = t[tx][i];
}

// Normalize rows of g_wt (= columns of W), round to tf32 in place. Warp/row.
__global__ void wt_norm(int dummy) {
    int warp = (blockIdx.x * blockDim.x + threadIdx.x) >> 5;
    int lane = threadIdx.x & 31;
    if (warp >= CPAD) return;
    float* wr = g_wt + (size_t)warp * DD;
    float v[8]; float s = 0.f;
    #pragma unroll
    for (int j = 0; j < 8; j++) { v[j] = wr[lane + 32 * j]; s += v[j] * v[j]; }
    #pragma unroll
    for (int o = 16; o; o >>= 1) s += __shfl_xor_sync(~0u, s, o);
    float inv = 1.0f / fmaxf(sqrtf(s), 1e-12f);
    #pragma unroll
    for (int j = 0; j < 8; j++) wr[lane + 32 * j] = to_tf32(v[j] * inv);
}

// ---------------------------------------------------------------------------
// Main: per CTA one (M=128, N=128) tile; mma.sync m16n8k8 tf32.
// 8 warps: mw = wid&3 (32 rows each), nw = wid>>2 (64 cols each).
// Accumulators in registers; epilogue = masked online softmax + margin + argmax.
__global__ __launch_bounds__(256, 2)
void main_kernel(int dummy) {
    extern __shared__ float sm[];
    float* As = sm;                    // [128][AST]
    float* Bs = sm + 128 * AST;        // [128][AST]
    __shared__ float red_m[128][8], red_s[128][8];
    __shared__ int   red_c[128][8];
    __shared__ int   labs[128];

    const int tid = threadIdx.x, wid = tid >> 5, lane = tid & 31;
    const int gid = lane >> 2, tidg = lane & 3;
    const int mw = wid & 3, nw = wid >> 2;
    const int nt = blockIdx.x, mt = blockIdx.y;
    const int r0 = mt * 128, c0 = nt * 128;

    if (tid < 128) labs[tid] = g_lab[r0 + tid];

    float d[2][8][4];
    #pragma unroll
    for (int tm = 0; tm < 2; tm++)
        #pragma unroll
        for (int tn = 0; tn < 8; tn++)
            #pragma unroll
            for (int c = 0; c < 4; c++) d[tm][tn][c] = 0.f;

    for (int kc = 0; kc < DD; kc += KC) {
        __syncthreads();
        // Stage A and B chunks: 128 rows x 64 floats each, float4 fills.
        #pragma unroll
        for (int t = 0; t < 8; t++) {
            int i = tid + t * 256;
            int row = i >> 4, f4 = i & 15;
            *(float4*)&As[row * AST + f4 * 4] =
                *(const float4*)(g_xn + (size_t)(r0 + row) * DD + kc + f4 * 4);
            *(float4*)&Bs[row * AST + f4 * 4] =
                *(const float4*)(g_wt + (size_t)(c0 + row) * DD + kc + f4 * 4);
        }
        __syncthreads();

        #pragma unroll
        for (int ks = 0; ks < KC; ks += 8) {
            u32 a[2][4];
            #pragma unroll
            for (int tm = 0; tm < 2; tm++) {
                int rb = mw * 32 + tm * 16 + gid;
                a[tm][0] = __float_as_uint(As[rb * AST + ks + tidg]);
                a[tm][1] = __float_as_uint(As[(rb + 8) * AST + ks + tidg]);
                a[tm][2] = __float_as_uint(As[rb * AST + ks + tidg + 4]);
                a[tm][3] = __float_as_uint(As[(rb + 8) * AST + ks + tidg + 4]);
            }
            #pragma unroll
            for (int tn = 0; tn < 8; tn++) {
                int nb = nw * 64 + tn * 8 + gid;
                u32 b0 = __float_as_uint(Bs[nb * AST + ks + tidg]);
                u32 b1 = __float_as_uint(Bs[nb * AST + ks + tidg + 4]);
                mma8(d[0][tn], a[0], b0, b1);
                mma8(d[1][tn], a[1], b0, b1);
            }
        }
    }

    // Epilogue: thread owns rows {mw*32 + tm*16 + rh*8 + gid}, 16 cols each.
    #pragma unroll
    for (int tm = 0; tm < 2; tm++) {
        #pragma unroll
        for (int rh = 0; rh < 2; rh++) {
            int rloc = mw * 32 + tm * 16 + rh * 8 + gid;
            int rg = r0 + rloc;
            int lab = labs[rloc];
            float m = -INFINITY, s = 0.f; int bc = 0x7fffffff;
            #pragma unroll
            for (int tn = 0; tn < 8; tn++) {
                #pragma unroll
                for (int c = 0; c < 2; c++) {
                    int cg = c0 + nw * 64 + tn * 8 + 2 * tidg + c;
                    if (cg < CC) {
                        float ct = fminf(fmaxf(d[tm][tn][rh * 2 + c], -1.0f + EPSC), 1.0f + EPSC);
                        float lg;
                        if (cg == lab) {
                            float s2 = 1.0f - ct * ct;
                            float sn = (s2 > 0.f) ? sqrtf(s2) : 0.f;
                            lg = (ct * COSM - sn * SINM) * SCL;
                            g_tgt[rg] = lg;
                        } else {
                            lg = ct * SCL;
                        }
                        if (lg > m) { s = s * __expf(m - lg) + 1.0f; m = lg; bc = cg; }
                        else        { s += __expf(lg - m); }
                    }
                }
            }
            int slot = nw * 4 + tidg;
            red_m[rloc][slot] = m; red_s[rloc][slot] = s; red_c[rloc][slot] = bc;
        }
    }
    __syncthreads();

    if (tid < 128) {
        const int rloc = tid, rg = r0 + rloc;
        float m = red_m[rloc][0], s = red_s[rloc][0]; int c = red_c[rloc][0];
        #pragma unroll
        for (int w = 1; w < 8; w++) {
            float om = red_m[rloc][w], os = red_s[rloc][w]; int oc = red_c[rloc][w];
            float M = fmaxf(m, om);
            s = s * __expf(m - M) + os * __expf(om - M);
            if (om > m) c = oc;
            m = M;
        }
        g_pm[(size_t)rg * NTILES + nt] = m;
        g_ps[(size_t)rg * NTILES + nt] = s;
        g_pc[(size_t)rg * NTILES + nt] = c;
    }
}

// ---------------------------------------------------------------------------
__global__ void combine_kernel(int dummy) {
    int r = blockIdx.x * 128 + threadIdx.x;
    if (r >= BB) return;
    float m = -INFINITY, s = 0.f; int c = 0x7fffffff;
    for (int j = 0; j < NTILES; j++) {
        float pm = g_pm[(size_t)r * NTILES + j];
        float ps = g_ps[(size_t)r * NTILES + j];
        int   pc = g_pc[(size_t)r * NTILES + j];
        float M = fmaxf(m, pm);
        s = s * __expf(m - M) + ps * __expf(pm - M);
        if (pm > m) c = pc;                 // ascending j => lowest class on tie
        m = M;
    }
    g_rowloss[r] = (m + logf(s)) - g_tgt[r];
    g_rowhit[r]  = (c == g_lab[r]) ? 1.0f : 0.0f;
}

__global__ void finalize_kernel(float* __restrict__ out) {
    __shared__ float sl[1024], sh[1024];
    int tid = threadIdx.x;
    float l = 0.f, h = 0.f;
    for (int i = tid; i < BB; i += 1024) { l += g_rowloss[i]; h += g_rowhit[i]; }
    sl[tid] = l; sh[tid] = h;
    __syncthreads();
    for (int o = 512; o; o >>= 1) {
        if (tid < o) { sl[tid] += sl[tid + o]; sh[tid] += sh[tid + o]; }
        __syncthreads();
    }
    if (tid == 0) {
        out[0] = sl[0] / (float)BB;
        out[1] = sh[0] * (100.0f / (float)BB);
    }
}

// ---------------------------------------------------------------------------
extern "C" void kernel_launch(void* const* d_in, const int* in_sizes, int n_in,
                              void* d_out, int out_size) {
    const float* x   = (const float*)d_in[0];
    const float* W   = (const float*)d_in[1];
    const int*   lab = (const int*)d_in[2];

    // Unconditional host-side attribute set (no static guards per harness rules).
    cudaFuncSetAttribute(main_kernel, cudaFuncAttributeMaxDynamicSharedMemorySize, SMEM_DYN);

    detect_kernel<<<1, 256>>>((const u32*)lab);                  // 1
    conv_labels<<<16, 256>>>(lab);                               // 2
    prep_x<<<512, 256>>>(x);                                     // 3
    wt_transpose<<<dim3(188, 8), dim3(32, 8)>>>(W);              // 4
    wt_norm<<<752, 256>>>(0);                                    // 5
    main_kernel<<<dim3(NTILES, MTILES), 256, SMEM_DYN>>>(0);     // 6 (ncu -s 5 slot)
    combine_kernel<<<32, 128>>>(0);                              // 7
    finalize_kernel<<<1, 1024>>>((float*)d_out);                 // 8
}

// round 13
// speedup vs baseline: 5.7265x; 1.0489x over previous
#include <cuda_runtime.h>
#include <math.h>
#include <stdint.h>

#define BB 4096
#define DD 256
#define CC 5994
#define CPAD 6016
#define NTILES 47
#define MTILES 32
#define SCL 30.0f
#define COSM 0.9800665778412416f
#define SINM 0.19866933079506122f
#define EPSC 1e-7f

#define KC 64          // k-chunk per smem stage
#define AST 68         // smem row stride (floats): bank=(4*row+k)%32, conflict-free
#define SMEM_DYN (2 * 128 * AST * 4)

typedef unsigned int u32;

__device__ int   g_is64;
__device__ int   g_lab[BB];
__device__ float g_xn[BB * DD];          // normalized x, tf32-rounded
__device__ float g_wt[CPAD * DD];        // W^T, normalized cols, tf32-rounded, zero-padded
__device__ float g_wsum[CPAD];           // column sum-of-squares of W (atomic partials)
__device__ float g_tgt[BB];              // margin logit of the label class per row
__device__ float g_pm[BB * NTILES];      // partial max
__device__ float g_ps[BB * NTILES];      // partial sum
__device__ int   g_pc[BB * NTILES];      // partial argmax (global class)
__device__ float g_accl, g_acch;         // final accumulators
__device__ int   g_done;                 // ticket counter

__device__ __forceinline__ float to_tf32(float v) {
    u32 u; asm("cvt.rna.tf32.f32 %0, %1;" : "=r"(u) : "f"(v));
    return __uint_as_float(u);
}
__device__ __forceinline__ u32 smem_u32(const void* p) {
    u32 a; asm("{ .reg .u64 t; cvta.to.shared.u64 t, %1; cvt.u32.u64 %0, t; }" : "=r"(a) : "l"(p));
    return a;
}
__device__ __forceinline__ void cp16(u32 saddr, const void* g) {
    asm volatile("cp.async.ca.shared.global [%0], [%1], 16;" :: "r"(saddr), "l"(g));
}

// m16n8k8 tf32 HMMA (baseline sm_80+ PTX; compiles for plain sm_103)
__device__ __forceinline__ void mma8(float* d, const u32* a, u32 b0, u32 b1) {
    asm volatile(
        "mma.sync.aligned.m16n8k8.row.col.f32.tf32.tf32.f32 "
        "{%0,%1,%2,%3}, {%4,%5,%6,%7}, {%8,%9}, {%0,%1,%2,%3};"
        : "+f"(d[0]), "+f"(d[1]), "+f"(d[2]), "+f"(d[3])
        : "r"(a[0]), "r"(a[1]), "r"(a[2]), "r"(a[3]), "r"(b0), "r"(b1));
}

// ---------------------------------------------------------------------------
// L1: label dtype detection + zero per-replay accumulators (graph-replay safe)
__global__ void detect_kernel(const u32* __restrict__ p) {
    int any = 0;
    for (int i = 1 + 2 * (int)threadIdx.x; i < BB; i += 2 * (int)blockDim.x)
        any |= (p[i] != 0u);
    int r = __syncthreads_or(any);
    if (threadIdx.x == 0) { g_is64 = (r == 0) ? 1 : 0; g_accl = 0.f; g_acch = 0.f; g_done = 0; }
    for (int i = threadIdx.x; i < CPAD; i += blockDim.x) g_wsum[i] = 0.f;
}

// ---------------------------------------------------------------------------
// L2: one grid, three roles by block range.
//   b <  512        : normalize x row-block (8 warps, 1 row/warp), tf32 round
//   512 <= b < 560  : W column sum-of-squares partials (48 blocks: 12 col-groups x 4 k-slices)
//   560 <= b < 576  : label gather (int64/int32)
__global__ void mega_prep(const float* __restrict__ x, const float* __restrict__ W,
                          const int* __restrict__ lab) {
    const int b = blockIdx.x, tid = threadIdx.x;
    if (b < 512) {
        int row = b * 8 + (tid >> 5);
        int lane = tid & 31;
        const float* xr = x + (size_t)row * DD;
        float v[8]; float s = 0.f;
        #pragma unroll
        for (int j = 0; j < 8; j++) { v[j] = xr[lane + 32 * j]; s += v[j] * v[j]; }
        #pragma unroll
        for (int o = 16; o; o >>= 1) s += __shfl_xor_sync(~0u, s, o);
        float inv = 1.0f / fmaxf(sqrtf(s), 1e-12f);
        #pragma unroll
        for (int j = 0; j < 8; j++) g_xn[(size_t)row * DD + lane + 32 * j] = to_tf32(v[j] * inv);
    } else if (b < 560) {
        int bx = b - 512;
        int cb = (bx >> 2) * 512;
        int k0 = (bx & 3) * 64;
        #pragma unroll
        for (int h = 0; h < 2; h++) {
            int c = cb + h * 256 + tid;
            if (c < CC) {
                float s = 0.f;
                const float* wp = W + (size_t)k0 * CC + c;
                #pragma unroll 8
                for (int k = 0; k < 64; k++) { float v = wp[(size_t)k * CC]; s += v * v; }
                atomicAdd(&g_wsum[c], s);
            }
        }
    } else {
        int i = (b - 560) * 256 + tid;
        if (i < BB) g_lab[i] = g_is64 ? lab[2 * i] : lab[i];
    }
}

// ---------------------------------------------------------------------------
// L3: transpose W [256, 5994] -> g_wt [6016, 256], normalize + tf32 round inline.
__global__ void wt_transpose_apply(const float* __restrict__ W) {
    __shared__ float t[32][33];
    int bx = blockIdx.x, by = blockIdx.y;
    int tx = threadIdx.x, ty = threadIdx.y;
    #pragma unroll
    for (int i = ty; i < 32; i += 8) {
        int k = by * 32 + i, c = bx * 32 + tx;
        t[i][tx] = (c < CC) ? W[(size_t)k * CC + c] : 0.f;
    }
    __syncthreads();
    #pragma unroll
    for (int i = ty; i < 32; i += 8) {
        int c = bx * 32 + i;                    // g_wt row = W column
        float inv = 1.0f / fmaxf(sqrtf(g_wsum[c]), 1e-12f);
        g_wt[(size_t)c * DD + by * 32 + tx] = to_tf32(t[tx][i] * inv);
    }
}

// ---------------------------------------------------------------------------
// L4 (ncu capture slot): per CTA one (M=128, N=128) tile; mma.sync m16n8k8 tf32.
// 8 warps: mw = wid&3 (32 rows each), nw = wid>>2 (64 cols each).
__global__ __launch_bounds__(256, 2)
void main_kernel(int dummy) {
    extern __shared__ float sm[];
    float* As = sm;                    // [128][AST]
    float* Bs = sm + 128 * AST;        // [128][AST]
    __shared__ float red_m[128][8], red_s[128][8];
    __shared__ int   red_c[128][8];
    __shared__ int   labs[128];

    const u32 Abase = smem_u32(As), Bbase = smem_u32(Bs);
    const int tid = threadIdx.x, wid = tid >> 5, lane = tid & 31;
    const int gid = lane >> 2, tidg = lane & 3;
    const int mw = wid & 3, nw = wid >> 2;
    const int nt = blockIdx.x, mt = blockIdx.y;
    const int r0 = mt * 128, c0 = nt * 128;

    if (tid < 128) labs[tid] = g_lab[r0 + tid];

    float d[2][8][4];
    #pragma unroll
    for (int tm = 0; tm < 2; tm++)
        #pragma unroll
        for (int tn = 0; tn < 8; tn++)
            #pragma unroll
            for (int c = 0; c < 4; c++) d[tm][tn][c] = 0.f;

    for (int kc = 0; kc < DD; kc += KC) {
        __syncthreads();
        #pragma unroll
        for (int t = 0; t < 8; t++) {
            int i = tid + t * 256;
            int row = i >> 4, f4 = i & 15;
            cp16(Abase + (u32)(row * AST + f4 * 4) * 4,
                 g_xn + (size_t)(r0 + row) * DD + kc + f4 * 4);
            cp16(Bbase + (u32)(row * AST + f4 * 4) * 4,
                 g_wt + (size_t)(c0 + row) * DD + kc + f4 * 4);
        }
        asm volatile("cp.async.commit_group;");
        asm volatile("cp.async.wait_group 0;" ::: "memory");
        __syncthreads();

        #pragma unroll
        for (int ks = 0; ks < KC; ks += 8) {
            u32 a[2][4];
            #pragma unroll
            for (int tm = 0; tm < 2; tm++) {
                int rb = mw * 32 + tm * 16 + gid;
                a[tm][0] = __float_as_uint(As[rb * AST + ks + tidg]);
                a[tm][1] = __float_as_uint(As[(rb + 8) * AST + ks + tidg]);
                a[tm][2] = __float_as_uint(As[rb * AST + ks + tidg + 4]);
                a[tm][3] = __float_as_uint(As[(rb + 8) * AST + ks + tidg + 4]);
            }
            #pragma unroll
            for (int tn = 0; tn < 8; tn++) {
                int nb = nw * 64 + tn * 8 + gid;
                u32 b0 = __float_as_uint(Bs[nb * AST + ks + tidg]);
                u32 b1 = __float_as_uint(Bs[nb * AST + ks + tidg + 4]);
                mma8(d[0][tn], a[0], b0, b1);
                mma8(d[1][tn], a[1], b0, b1);
            }
        }
    }

    // Epilogue: thread owns rows {mw*32 + tm*16 + rh*8 + gid}, 16 cols each.
    #pragma unroll
    for (int tm = 0; tm < 2; tm++) {
        #pragma unroll
        for (int rh = 0; rh < 2; rh++) {
            int rloc = mw * 32 + tm * 16 + rh * 8 + gid;
            int rg = r0 + rloc;
            int lab = labs[rloc];
            float m = -INFINITY, s = 0.f; int bc = 0x7fffffff;
            #pragma unroll
            for (int tn = 0; tn < 8; tn++) {
                #pragma unroll
                for (int c = 0; c < 2; c++) {
                    int cg = c0 + nw * 64 + tn * 8 + 2 * tidg + c;
                    if (cg < CC) {
                        float ct = fminf(fmaxf(d[tm][tn][rh * 2 + c], -1.0f + EPSC), 1.0f + EPSC);
                        float lg;
                        if (cg == lab) {
                            float s2 = 1.0f - ct * ct;
                            float sn = (s2 > 0.f) ? sqrtf(s2) : 0.f;
                            lg = (ct * COSM - sn * SINM) * SCL;
                            g_tgt[rg] = lg;
                        } else {
                            lg = ct * SCL;
                        }
                        if (lg > m) { s = s * __expf(m - lg) + 1.0f; m = lg; bc = cg; }
                        else        { s += __expf(lg - m); }
                    }
                }
            }
            int slot = nw * 4 + tidg;
            red_m[rloc][slot] = m; red_s[rloc][slot] = s; red_c[rloc][slot] = bc;
        }
    }
    __syncthreads();

    if (tid < 128) {
        const int rloc = tid, rg = r0 + rloc;
        float m = red_m[rloc][0], s = red_s[rloc][0]; int c = red_c[rloc][0];
        #pragma unroll
        for (int w = 1; w < 8; w++) {
            float om = red_m[rloc][w], os = red_s[rloc][w]; int oc = red_c[rloc][w];
            float M = fmaxf(m, om);
            s = s * __expf(m - M) + os * __expf(om - M);
            if (om > m) c = oc;
            m = M;
        }
        g_pm[(size_t)rg * NTILES + nt] = m;
        g_ps[(size_t)rg * NTILES + nt] = s;
        g_pc[(size_t)rg * NTILES + nt] = c;
    }
}

// ---------------------------------------------------------------------------
// L5: combine tile partials -> per-row loss/hit -> block reduce -> atomic
// accumulate; last block (ticket) writes the 2-element output.
__global__ void combine_final(float* __restrict__ out) {
    __shared__ float sl[128], sh[128];
    const int tid = threadIdx.x;
    const int r = blockIdx.x * 128 + tid;

    float m = -INFINITY, s = 0.f; int c = 0x7fffffff;
    for (int j = 0; j < NTILES; j++) {
        float pm = g_pm[(size_t)r * NTILES + j];
        float ps = g_ps[(size_t)r * NTILES + j];
        int   pc = g_pc[(size_t)r * NTILES + j];
        float M = fmaxf(m, pm);
        s = s * __expf(m - M) + ps * __expf(pm - M);
        if (pm > m) c = pc;                 // ascending j => lowest class on tie
        m = M;
    }
    sl[tid] = (m + logf(s)) - g_tgt[r];
    sh[tid] = (c == g_lab[r]) ? 1.0f : 0.0f;
    __syncthreads();
    for (int o = 64; o; o >>= 1) {
        if (tid < o) { sl[tid] += sl[tid + o]; sh[tid] += sh[tid + o]; }
        __syncthreads();
    }
    if (tid == 0) {
        atomicAdd(&g_accl, sl[0]);
        atomicAdd(&g_acch, sh[0]);
        __threadfence();
        int ticket = atomicAdd(&g_done, 1);
        if (ticket == (int)gridDim.x - 1) {
            float l = atomicAdd(&g_accl, 0.f);   // fenced read-after-all-arrivals
            float h = atomicAdd(&g_acch, 0.f);
            out[0] = l / (float)BB;
            out[1] = h * (100.0f / (float)BB);
        }
    }
}

// ---------------------------------------------------------------------------
extern "C" void kernel_launch(void* const* d_in, const int* in_sizes, int n_in,
                              void* d_out, int out_size) {
    const float* x   = (const float*)d_in[0];
    const float* W   = (const float*)d_in[1];
    const int*   lab = (const int*)d_in[2];

    cudaFuncSetAttribute(main_kernel, cudaFuncAttributeMaxDynamicSharedMemorySize, SMEM_DYN);

    detect_kernel<<<1, 256>>>((const u32*)lab);                  // 1
    mega_prep<<<576, 256>>>(x, W, lab);                          // 2
    wt_transpose_apply<<<dim3(188, 8), dim3(32, 8)>>>(W);        // 3
    main_kernel<<<dim3(NTILES, MTILES), 256, SMEM_DYN>>>(0);     // 4  <- ncu capture slot
    combine_final<<<32, 128>>>((float*)d_out);                   // 5
}